// round 14
// baseline (speedup 1.0000x reference)
#include <cuda_runtime.h>
#include <cuda_bf16.h>
#include <math_constants.h>
#include <cstdint>

// ---------------- problem constants ----------------
#define NN 8192      // 2*B rows
#define BB 4096
#define DD 256
#define NP 64        // 128-row panels
#define NCTA 148     // 296 warpgroups; 2080 = 296*7 + 8 upper-tri tiles
#define CREF 192.0f  // fixed log2-domain exp reference

// ---------------- device scratch ----------------
__device__ __nv_bfloat16 g_hb[NN * DD];        // sqrt(2*log2e)*h in bf16
__device__ float g_ps[NP * NP * 128];          // per (rowPanel,colPanel) partial sum
__device__ float g_pos[NN];                    // positive logit minus CREF
__device__ double g_part[32];
__device__ unsigned int g_cnt;

__device__ __forceinline__ uint32_t smem_u32(const void* p) {
    uint32_t a;
    asm("{ .reg .u64 t; cvta.to.shared.u64 t, %1; cvt.u32.u64 %0, t; }" : "=r"(a) : "l"(p));
    return a;
}

__device__ __forceinline__ void ldsm_x4(uint32_t* r, uint32_t addr) {
    asm volatile("ldmatrix.sync.aligned.m8n8.x4.shared.b16 {%0,%1,%2,%3}, [%4];"
        : "=r"(r[0]), "=r"(r[1]), "=r"(r[2]), "=r"(r[3]) : "r"(addr));
}

__device__ __forceinline__ void mma16816(float* c, const uint32_t* a,
                                         uint32_t b0, uint32_t b1) {
    asm volatile(
        "mma.sync.aligned.m16n8k16.row.col.f32.bf16.bf16.f32 "
        "{%0,%1,%2,%3}, {%4,%5,%6,%7}, {%8,%9}, {%0,%1,%2,%3};"
        : "+f"(c[0]), "+f"(c[1]), "+f"(c[2]), "+f"(c[3])
        : "r"(a[0]), "r"(a[1]), "r"(a[2]), "r"(a[3]), "r"(b0), "r"(b1));
}

// d = a*b + (-CREF)
__device__ __forceinline__ void mma16816_c(float* d, const uint32_t* a,
                                           uint32_t b0, uint32_t b1, float cinit) {
    asm volatile(
        "mma.sync.aligned.m16n8k16.row.col.f32.bf16.bf16.f32 "
        "{%0,%1,%2,%3}, {%4,%5,%6,%7}, {%8,%9}, {%10,%11,%12,%13};"
        : "=f"(d[0]), "=f"(d[1]), "=f"(d[2]), "=f"(d[3])
        : "r"(a[0]), "r"(a[1]), "r"(a[2]), "r"(a[3]), "r"(b0), "r"(b1),
          "f"(cinit), "f"(cinit), "f"(cinit), "f"(cinit));
}

__device__ __forceinline__ float fex2(float x) {
    float y;
    asm("ex2.approx.f32 %0, %1;" : "=f"(y) : "f"(x));
    return y;
}

// A tile: 128 rows x 512B (256 bf16); B half: 128 rows x 256B (128 bf16)
#define TSWZ(r, kb)  ((r) * 512 + ((kb) ^ (((r) & 7) << 4)))
#define SW256(r, kb) ((r) * 256 + ((kb) ^ (((r) & 7) << 4)))

// 256-thread (one WG) loaders
__device__ __forceinline__ void load_A(uint32_t sdst, const __nv_bfloat16* gbase,
                                       int wtid) {
#pragma unroll
    for (int i = 0; i < 16; ++i) {
        int c = wtid + i * 256;
        int r = c >> 5;
        int kb = (c & 31) << 4;
        uint32_t dst = sdst + TSWZ(r, kb);
        const char* src = (const char*)(gbase + (size_t)r * DD) + kb;
        asm volatile("cp.async.cg.shared.global [%0], [%1], 16;" :: "r"(dst), "l"(src));
    }
}

// B half: 128 rows x 256 bytes = 2048 16B chunks, 16 chunks per row
__device__ __forceinline__ void load_half(uint32_t sdst, const __nv_bfloat16* gbase,
                                          int koff, int wtid) {
#pragma unroll
    for (int i = 0; i < 8; ++i) {
        int c = wtid + i * 256;
        int r = c >> 4;                 // 0..127
        int kb = (c & 15) << 4;         // 0..240
        uint32_t dst = sdst + SW256(r, kb);
        const char* src = (const char*)(gbase + (size_t)r * DD) + koff + kb;
        asm volatile("cp.async.cg.shared.global [%0], [%1], 16;" :: "r"(dst), "l"(src));
    }
}

// ---------------- kernel 0: fp32 -> sqrt(2*log2e)*bf16 ----------------
__global__ __launch_bounds__(256) void convert_bf16(const float* __restrict__ h_i,
                                                    const float* __restrict__ h_j) {
    int v = blockIdx.x * 256 + threadIdx.x;
    int row = v >> 6;
    int c4 = v & 63;
    const float* src = (row < BB) ? h_i + (size_t)row * DD : h_j + (size_t)(row - BB) * DD;
    float4 x = *(const float4*)(src + c4 * 4);
    const float s = 1.6986436f;               // sqrt(2 * log2(e))
    __nv_bfloat162 p0 = __nv_bfloat162(__float2bfloat16(x.x * s), __float2bfloat16(x.y * s));
    __nv_bfloat162 p1 = __nv_bfloat162(__float2bfloat16(x.z * s), __float2bfloat16(x.w * s));
    uint2* dst = (uint2*)(g_hb + (size_t)row * DD + c4 * 4);
    uint2 w;
    w.x = *(uint32_t*)&p0;
    w.y = *(uint32_t*)&p1;
    *dst = w;
}

// ---------------- kernel 1: two independent warpgroups, staggered tiles ----------
// smem: A0 64K | A1 64K | B0 32K | B1 32K | rowS0/1 2K each | colS0/1 1K each
#define OFF_B    131072
#define OFF_ROWS 196608
#define OFF_COLS 200704
#define SMEM_BYTES 202752

__global__ __launch_bounds__(512, 1) void gemm_lse_sym() {
    extern __shared__ char smem[];
    const int tid = threadIdx.x;
    const int wgid = tid >> 8;            // 0 or 1
    const int wtid = tid & 255;
    const int lane = tid & 31;
    const int wid = wtid >> 5;            // 0..7 within WG
    const int warp_m = wid >> 2;
    const int warp_n = wid & 3;

    const uint32_t sbA = smem_u32(smem) + wgid * 65536;
    const uint32_t sbB = smem_u32(smem) + OFF_B + wgid * 32768;
    float* rowS = (float*)(smem + OFF_ROWS + wgid * 2048);   // [4 slabs][128]
    float* colS = (float*)(smem + OFF_COLS + wgid * 1024);   // [2 slabs][128]

#define WGBAR() asm volatile("bar.sync %0, 256;" :: "r"(wgid + 1) : "memory")

    // global warpgroup id and its contiguous tile range (2080 = 296*7 + 8)
    const int g = blockIdx.x * 2 + wgid;
    const int cnt = 7 + (g < 8 ? 1 : 0);
    int rem = g * 7 + (g < 8 ? g : 8);
    int I = 0, L = NP;
    while (rem >= L) { rem -= L; ++I; --L; }
    int J = I + rem;

    // prologue: A(I) + B half1(tile0) in one group
    load_A(sbA, g_hb + (size_t)I * 128 * DD, wtid);
    load_half(sbB, g_hb + (size_t)J * 128 * DD, 0, wtid);
    asm volatile("cp.async.commit_group;");

    const int lrA = (lane & 7) + ((lane >> 3) & 1) * 8;
    const int kA  = (lane >> 4) * 16;
    const int lnB = (lane & 7) + ((lane >> 4) << 3);
    const int kB  = ((lane >> 3) & 1) * 16;
    const int rquad = lane >> 2;
    const int cquad = (lane & 3) * 2;

    int Ip = 0, Jp = 0;
    bool diagPrev = true;

    for (int t = 0; t < cnt; ++t) {
        int In = I, Jn = J + 1;
        if (Jn == NP) { In = I + 1; Jn = In; }

        // wait half1(t) (+A); all warps ready
        asm volatile("cp.async.wait_group 0;");
        WGBAR();

        // deferred merge of tile t-1 (off the tensor critical path)
        if (t > 0) {
            if (wtid < 128) {
                g_ps[((size_t)Ip * NP + Jp) * 128 + wtid] =
                    rowS[wtid] + rowS[128 + wtid] + rowS[256 + wtid] + rowS[384 + wtid];
            } else if (!diagPrev) {
                const int cl = wtid - 128;
                g_ps[((size_t)Jp * NP + Ip) * 128 + cl] = colS[cl] + colS[128 + cl];
            }
        }

        float c[4][4][4];
        // ---- phase 1: k in [0,128) ----
#pragma unroll
        for (int ks = 0; ks < 8; ++ks) {
            uint32_t a[4][4], b[2][4];
#pragma unroll
            for (int mt = 0; mt < 4; ++mt)
                ldsm_x4(a[mt], sbA + TSWZ(warp_m * 64 + mt * 16 + lrA, ks * 32 + kA));
#pragma unroll
            for (int p = 0; p < 2; ++p)
                ldsm_x4(b[p], sbB + SW256(warp_n * 32 + p * 16 + lnB, ks * 32 + kB));
#pragma unroll
            for (int mt = 0; mt < 4; ++mt)
#pragma unroll
                for (int nt = 0; nt < 4; ++nt) {
                    if (ks == 0)
                        mma16816_c(c[mt][nt], a[mt],
                                   b[nt >> 1][(nt & 1) * 2], b[nt >> 1][(nt & 1) * 2 + 1],
                                   -CREF);
                    else
                        mma16816(c[mt][nt], a[mt],
                                 b[nt >> 1][(nt & 1) * 2], b[nt >> 1][(nt & 1) * 2 + 1]);
                }
        }
        WGBAR();   // phase-1 reads done; B buffer free

        // load half2(t) into same buffer
        load_half(sbB, g_hb + (size_t)J * 128 * DD, 256, wtid);   // koff 256B = k elem 128
        asm volatile("cp.async.commit_group;");
        asm volatile("cp.async.wait_group 0;");
        WGBAR();

        // ---- phase 2: k in [128,256) ----
#pragma unroll
        for (int ks = 0; ks < 8; ++ks) {
            uint32_t a[4][4], b[2][4];
#pragma unroll
            for (int mt = 0; mt < 4; ++mt)
                ldsm_x4(a[mt], sbA + TSWZ(warp_m * 64 + mt * 16 + lrA, (ks + 8) * 32 + kA));
#pragma unroll
            for (int p = 0; p < 2; ++p)
                ldsm_x4(b[p], sbB + SW256(warp_n * 32 + p * 16 + lnB, ks * 32 + kB));
#pragma unroll
            for (int mt = 0; mt < 4; ++mt)
#pragma unroll
                for (int nt = 0; nt < 4; ++nt)
                    mma16816(c[mt][nt], a[mt],
                             b[nt >> 1][(nt & 1) * 2], b[nt >> 1][(nt & 1) * 2 + 1]);
        }
        WGBAR();   // phase-2 reads done; B (and A, if advancing) free

        // prefetch next tile: half1(t+1) (+ A panel if it advances), overlapped with epilogue
        if (t + 1 < cnt) {
            load_half(sbB, g_hb + (size_t)Jn * 128 * DD, 0, wtid);
            if (In != I) load_A(sbA, g_hb + (size_t)In * 128 * DD, wtid);
        }
        asm volatile("cp.async.commit_group;");

        // ---- epilogue ----
        const bool diagT = (J == I);
        const bool posT  = (J == I + NP / 2);

        if (diagT | posT) {
#pragma unroll
            for (int mt = 0; mt < 4; ++mt)
#pragma unroll
                for (int jj = 0; jj < 2; ++jj) {
                    const int rloc = warp_m * 64 + mt * 16 + rquad + jj * 8;
#pragma unroll
                    for (int nt = 0; nt < 4; ++nt)
#pragma unroll
                        for (int jc = 0; jc < 2; ++jc) {
                            const int cloc = warp_n * 32 + nt * 8 + cquad + jc;
                            if (cloc == rloc) {
                                float v = c[mt][nt][jj * 2 + jc];
                                if (posT) {
                                    g_pos[I * 128 + rloc] = v;   // pos - CREF
                                    g_pos[J * 128 + rloc] = v;
                                } else {
                                    c[mt][nt][jj * 2 + jc] = -CUDART_INF_F;
                                }
                            }
                        }
                }
        }

#pragma unroll
        for (int mt = 0; mt < 4; ++mt)
#pragma unroll
            for (int nt = 0; nt < 4; ++nt)
#pragma unroll
                for (int k = 0; k < 4; ++k)
                    c[mt][nt][k] = fex2(c[mt][nt][k]);

#pragma unroll
        for (int mt = 0; mt < 4; ++mt)
#pragma unroll
            for (int jj = 0; jj < 2; ++jj) {
                float s = 0.f;
#pragma unroll
                for (int nt = 0; nt < 4; ++nt)
#pragma unroll
                    for (int jc = 0; jc < 2; ++jc)
                        s += c[mt][nt][jj * 2 + jc];
                s += __shfl_xor_sync(0xffffffffu, s, 1);
                s += __shfl_xor_sync(0xffffffffu, s, 2);
                if ((lane & 3) == 0) {
                    const int rloc = warp_m * 64 + mt * 16 + rquad + jj * 8;
                    rowS[warp_n * 128 + rloc] = s;
                }
            }

        if (!diagT) {
#pragma unroll
            for (int nt = 0; nt < 4; ++nt)
#pragma unroll
                for (int jc = 0; jc < 2; ++jc) {
                    float cs = 0.f;
#pragma unroll
                    for (int mt = 0; mt < 4; ++mt)
#pragma unroll
                        for (int jj = 0; jj < 2; ++jj)
                            cs += c[mt][nt][jj * 2 + jc];
                    cs += __shfl_xor_sync(0xffffffffu, cs, 4);
                    cs += __shfl_xor_sync(0xffffffffu, cs, 8);
                    cs += __shfl_xor_sync(0xffffffffu, cs, 16);
                    if (lane < 4) {
                        const int cloc = warp_n * 32 + nt * 8 + (lane & 3) * 2 + jc;
                        colS[warp_m * 128 + cloc] = cs;
                    }
                }
        }

        Ip = I; Jp = J; diagPrev = diagT;
        I = In; J = Jn;
    }

    // final tile's merge
    WGBAR();
    if (wtid < 128) {
        g_ps[((size_t)Ip * NP + Jp) * 128 + wtid] =
            rowS[wtid] + rowS[128 + wtid] + rowS[256 + wtid] + rowS[384 + wtid];
    } else if (!diagPrev) {
        const int cl = wtid - 128;
        g_ps[((size_t)Jp * NP + Ip) * 128 + cl] = colS[cl] + colS[128 + cl];
    }
#undef WGBAR
}

// ---------------- fused finalize: per-row lse - pos, chip-wide double sum ----------
__global__ __launch_bounds__(256) void finalize_all(float* __restrict__ out) {
    __shared__ double red[256];
    __shared__ int s_last;
    const int tid = threadIdx.x;
    const int row = blockIdx.x * 256 + tid;
    const int R = row >> 7;
    const int rl = row & 127;
    const float* ps = g_ps + (size_t)R * NP * 128 + rl;
    float S = 0.f;
#pragma unroll 8
    for (int c = 0; c < NP; ++c) S += ps[c * 128];
    red[tid] = (double)((__log2f(S) - g_pos[row]) * 0.69314718055994531f);
    __syncthreads();
    for (int s = 128; s > 0; s >>= 1) {
        if (tid < s) red[tid] += red[tid + s];
        __syncthreads();
    }
    if (tid == 0) {
        g_part[blockIdx.x] = red[0];
        __threadfence();
        unsigned int old = atomicAdd(&g_cnt, 1u);
        s_last = (((old + 1) & 31) == 0);
    }
    __syncthreads();
    if (s_last && tid < 32) {
        double v = g_part[tid];
#pragma unroll
        for (int off = 16; off > 0; off >>= 1)
            v += __shfl_down_sync(0xffffffffu, v, off);
        if (tid == 0) out[0] = (float)(v / (double)NN);
    }
}

extern "C" void kernel_launch(void* const* d_in, const int* in_sizes, int n_in,
                              void* d_out, int out_size) {
    const float* h_i = (const float*)d_in[0];
    const float* h_j = (const float*)d_in[1];
    (void)in_sizes; (void)n_in; (void)out_size;

    static bool attr_set = false;
    if (!attr_set) {
        cudaFuncSetAttribute(gemm_lse_sym, cudaFuncAttributeMaxDynamicSharedMemorySize,
                             SMEM_BYTES);
        attr_set = true;
    }

    convert_bf16<<<2048, 256>>>(h_i, h_j);
    gemm_lse_sym<<<NCTA, 512, SMEM_BYTES>>>();
    finalize_all<<<32, 256>>>((float*)d_out);
}

// round 15
// speedup vs baseline: 1.5299x; 1.5299x over previous
#include <cuda_runtime.h>
#include <cuda_bf16.h>
#include <math_constants.h>
#include <cstdint>

// ---------------- problem constants ----------------
#define NN 8192      // 2*B rows
#define BB 4096
#define DD 256
#define NP 64        // 128-row panels
#define NCTA 148     // 148 CTAs; 2080 = 148*14 + 8 upper-tri tiles
#define CREF 192.0f  // fixed log2-domain exp reference

// ---------------- device scratch ----------------
__device__ __nv_bfloat16 g_hb[NN * DD];        // sqrt(2*log2e)*h in bf16
__device__ float g_ps[NP * NP * 128];          // per (rowPanel,colPanel) partial sum
__device__ float g_pos[NN];                    // positive logit minus CREF
__device__ double g_part[32];
__device__ unsigned int g_cnt;

__device__ __forceinline__ uint32_t smem_u32(const void* p) {
    uint32_t a;
    asm("{ .reg .u64 t; cvta.to.shared.u64 t, %1; cvt.u32.u64 %0, t; }" : "=r"(a) : "l"(p));
    return a;
}

__device__ __forceinline__ void ldsm_x4(uint32_t* r, uint32_t addr) {
    asm volatile("ldmatrix.sync.aligned.m8n8.x4.shared.b16 {%0,%1,%2,%3}, [%4];"
        : "=r"(r[0]), "=r"(r[1]), "=r"(r[2]), "=r"(r[3]) : "r"(addr));
}

__device__ __forceinline__ void mma16816(float* c, const uint32_t* a,
                                         uint32_t b0, uint32_t b1) {
    asm volatile(
        "mma.sync.aligned.m16n8k16.row.col.f32.bf16.bf16.f32 "
        "{%0,%1,%2,%3}, {%4,%5,%6,%7}, {%8,%9}, {%0,%1,%2,%3};"
        : "+f"(c[0]), "+f"(c[1]), "+f"(c[2]), "+f"(c[3])
        : "r"(a[0]), "r"(a[1]), "r"(a[2]), "r"(a[3]), "r"(b0), "r"(b1));
}

// d = a*b + (-CREF)
__device__ __forceinline__ void mma16816_c(float* d, const uint32_t* a,
                                           uint32_t b0, uint32_t b1, float cinit) {
    asm volatile(
        "mma.sync.aligned.m16n8k16.row.col.f32.bf16.bf16.f32 "
        "{%0,%1,%2,%3}, {%4,%5,%6,%7}, {%8,%9}, {%10,%11,%12,%13};"
        : "=f"(d[0]), "=f"(d[1]), "=f"(d[2]), "=f"(d[3])
        : "r"(a[0]), "r"(a[1]), "r"(a[2]), "r"(a[3]), "r"(b0), "r"(b1),
          "f"(cinit), "f"(cinit), "f"(cinit), "f"(cinit));
}

__device__ __forceinline__ float fex2(float x) {
    float y;
    asm("ex2.approx.f32 %0, %1;" : "=f"(y) : "f"(x));
    return y;
}

#define TSWZ(r, kb) ((r) * 512 + ((kb) ^ (((r) & 7) << 4)))

__device__ __forceinline__ void load_tile(uint32_t sdst, const __nv_bfloat16* gbase,
                                          int tid) {
#pragma unroll
    for (int i = 0; i < 16; ++i) {
        int c = tid + i * 256;
        int r = c >> 5;
        int kb = (c & 31) << 4;
        uint32_t dst = sdst + TSWZ(r, kb);
        const char* src = (const char*)(gbase + (size_t)r * DD) + kb;
        asm volatile("cp.async.cg.shared.global [%0], [%1], 16;" :: "r"(dst), "l"(src));
    }
}

// ---------------- kernel 0: fp32 -> sqrt(2*log2e)*bf16 ----------------
__global__ __launch_bounds__(256) void convert_bf16(const float* __restrict__ h_i,
                                                    const float* __restrict__ h_j) {
    int v = blockIdx.x * 256 + threadIdx.x;
    int row = v >> 6;
    int c4 = v & 63;
    const float* src = (row < BB) ? h_i + (size_t)row * DD : h_j + (size_t)(row - BB) * DD;
    float4 x = *(const float4*)(src + c4 * 4);
    const float s = 1.6986436f;               // sqrt(2 * log2(e))
    __nv_bfloat162 p0 = __nv_bfloat162(__float2bfloat16(x.x * s), __float2bfloat16(x.y * s));
    __nv_bfloat162 p1 = __nv_bfloat162(__float2bfloat16(x.z * s), __float2bfloat16(x.w * s));
    uint2* dst = (uint2*)(g_hb + (size_t)row * DD + c4 * 4);
    uint2 w;
    w.x = *(uint32_t*)&p0;
    w.y = *(uint32_t*)&p1;
    *dst = w;
}

// ---------------- kernel 1: symmetric bf16 GEMM, per-SMSP staggered epilogue -------
// smem: A 64KB | B0 64KB | B1 64KB | rowS[3][512] 6KB | colS[3][256] 3KB
#define OFF_ROWS 196608
#define OFF_COLS (OFF_ROWS + 6144)
#define SMEM_BYTES (OFF_COLS + 3072)

__global__ __launch_bounds__(256, 1) void gemm_lse_sym() {
    extern __shared__ char smem[];
    const uint32_t sbA = smem_u32(smem);
    const uint32_t sbB0 = sbA + 65536;
    const uint32_t sbB1 = sbA + 131072;
    float* rowSb = (float*)(smem + OFF_ROWS);   // [3 slots][4 slabs][128]
    float* colSb = (float*)(smem + OFF_COLS);   // [3 slots][2 slabs][128]

    const int tid = threadIdx.x;
    const int lane = tid & 31;
    const int wid = tid >> 5;
    const int warp_m = wid >> 2;   // SMSP = wid&3 hosts one warp of each warp_m
    const int warp_n = wid & 3;

    // per-CTA contiguous range of upper-tri tiles (2080 = 148*14 + 8)
    const int cta = blockIdx.x;
    const int cnt = 14 + (cta < 8 ? 1 : 0);
    int rem = cta * 14 + (cta < 8 ? cta : 8);
    int Ic = 0, L = NP;
    while (rem >= L) { rem -= L; ++Ic; --L; }
    int Jc = Ic + rem;

    load_tile(sbA, g_hb + (size_t)Ic * 128 * DD, tid);
    load_tile(sbB0, g_hb + (size_t)Jc * 128 * DD, tid);
    asm volatile("cp.async.commit_group;");

    const int lrA = (lane & 7) + ((lane >> 3) & 1) * 8;
    const int kA  = (lane >> 4) * 16;
    const int lnB = (lane & 7) + ((lane >> 4) << 3);
    const int kB  = ((lane >> 3) & 1) * 16;
    const int rquad = lane >> 2;
    const int cquad = (lane & 3) * 2;

    float c[4][4][4];

    // epilogue of tile (Ie,Je) on current c, writing partials to slot s
    auto do_epi = [&](int Ie, int Je, int s) {
        const bool diagT = (Je == Ie);
        const bool posT  = (Je == Ie + NP / 2);
        if (diagT | posT) {
#pragma unroll
            for (int mt = 0; mt < 4; ++mt)
#pragma unroll
                for (int jj = 0; jj < 2; ++jj) {
                    const int rloc = warp_m * 64 + mt * 16 + rquad + jj * 8;
#pragma unroll
                    for (int nt = 0; nt < 4; ++nt)
#pragma unroll
                        for (int jc = 0; jc < 2; ++jc) {
                            const int cloc = warp_n * 32 + nt * 8 + cquad + jc;
                            if (cloc == rloc) {
                                float v = c[mt][nt][jj * 2 + jc];
                                if (posT) {
                                    g_pos[Ie * 128 + rloc] = v;   // pos - CREF
                                    g_pos[Je * 128 + rloc] = v;
                                } else {
                                    c[mt][nt][jj * 2 + jc] = -CUDART_INF_F;
                                }
                            }
                        }
                }
        }
#pragma unroll
        for (int mt = 0; mt < 4; ++mt)
#pragma unroll
            for (int nt = 0; nt < 4; ++nt)
#pragma unroll
                for (int k = 0; k < 4; ++k)
                    c[mt][nt][k] = fex2(c[mt][nt][k]);

        float* rS = rowSb + s * 512;
        float* cS = colSb + s * 256;
#pragma unroll
        for (int mt = 0; mt < 4; ++mt)
#pragma unroll
            for (int jj = 0; jj < 2; ++jj) {
                float sm = 0.f;
#pragma unroll
                for (int nt = 0; nt < 4; ++nt)
#pragma unroll
                    for (int jc = 0; jc < 2; ++jc)
                        sm += c[mt][nt][jj * 2 + jc];
                sm += __shfl_xor_sync(0xffffffffu, sm, 1);
                sm += __shfl_xor_sync(0xffffffffu, sm, 2);
                if ((lane & 3) == 0) {
                    const int rloc = warp_m * 64 + mt * 16 + rquad + jj * 8;
                    rS[warp_n * 128 + rloc] = sm;
                }
            }
        if (!diagT) {
#pragma unroll
            for (int nt = 0; nt < 4; ++nt)
#pragma unroll
                for (int jc = 0; jc < 2; ++jc) {
                    float cs = 0.f;
#pragma unroll
                    for (int mt = 0; mt < 4; ++mt)
#pragma unroll
                        for (int jj = 0; jj < 2; ++jj)
                            cs += c[mt][nt][jj * 2 + jc];
                    cs += __shfl_xor_sync(0xffffffffu, cs, 4);
                    cs += __shfl_xor_sync(0xffffffffu, cs, 8);
                    cs += __shfl_xor_sync(0xffffffffu, cs, 16);
                    if (lane < 4) {
                        const int cloc = warp_n * 32 + nt * 8 + (lane & 3) * 2 + jc;
                        cS[warp_m * 128 + cloc] = cs;
                    }
                }
        }
    };

    auto run_mma = [&](uint32_t sbB) {
#pragma unroll
        for (int ks = 0; ks < 16; ++ks) {
            uint32_t a[4][4], b[2][4];
#pragma unroll
            for (int mt = 0; mt < 4; ++mt)
                ldsm_x4(a[mt], sbA + TSWZ(warp_m * 64 + mt * 16 + lrA, ks * 32 + kA));
#pragma unroll
            for (int p = 0; p < 2; ++p)
                ldsm_x4(b[p], sbB + TSWZ(warp_n * 32 + p * 16 + lnB, ks * 32 + kB));
#pragma unroll
            for (int mt = 0; mt < 4; ++mt)
#pragma unroll
                for (int nt = 0; nt < 4; ++nt) {
                    if (ks == 0)
                        mma16816_c(c[mt][nt], a[mt],
                                   b[nt >> 1][(nt & 1) * 2], b[nt >> 1][(nt & 1) * 2 + 1],
                                   -CREF);
                    else
                        mma16816(c[mt][nt], a[mt],
                                 b[nt >> 1][(nt & 1) * 2], b[nt >> 1][(nt & 1) * 2 + 1]);
                }
        }
    };

    auto do_merge = [&](int Im, int Jm, bool diagM, int s) {
        const float* rS = rowSb + s * 512;
        const float* cS = colSb + s * 256;
        if (tid < 128) {
            g_ps[((size_t)Im * NP + Jm) * 128 + tid] =
                rS[tid] + rS[128 + tid] + rS[256 + tid] + rS[384 + tid];
        } else if (!diagM) {
            const int cl = tid - 128;
            g_ps[((size_t)Jm * NP + Im) * 128 + cl] = cS[cl] + cS[128 + cl];
        }
    };

    int I1 = 0, J1 = 0, I2 = 0, J2 = 0;
    bool d1 = true, d2 = true;

    for (int t = 0; t < cnt; ++t) {
        int In = Ic, Jn = Jc + 1;
        if (Jn == NP) { In = Ic + 1; Jn = In; }

        asm volatile("cp.async.wait_group 0;");   // B(t) (+A) fully arrived
        __syncthreads();

        // issue B(t+1) AFTER the barrier: buffer (t+1)&1's last reader
        // (warp_m=1's mma(t-1)) is provably done.
        if (t + 1 < cnt) {
            load_tile(((t + 1) & 1) ? sbB1 : sbB0, g_hb + (size_t)Jn * 128 * DD, tid);
            asm volatile("cp.async.commit_group;");
        }

        if (t >= 2) do_merge(I2, J2, d2, (t - 2) % 3);

        const uint32_t sbB = (t & 1) ? sbB1 : sbB0;
        if (warp_m == 0) {
            run_mma(sbB);             // tensor first...
            do_epi(Ic, Jc, t % 3);    // ...epilogue under mate's mma
        } else {
            if (t > 0) do_epi(I1, J1, (t - 1) % 3);   // epilogue under mate's mma
            run_mma(sbB);             // tensor second
        }

        if (t + 1 < cnt && In != Ic) {   // A-panel advance: all mma(t) done by here
            __syncthreads();
            load_tile(sbA, g_hb + (size_t)In * 128 * DD, tid);
            asm volatile("cp.async.commit_group;");
        }

        I2 = I1; J2 = J1; d2 = d1;
        I1 = Ic; J1 = Jc; d1 = (Jc == Ic);
        Ic = In; Jc = Jn;
    }

    // tail: flush warp_m=1's last epilogue and the two pending merges
    __syncthreads();
    if (cnt >= 2) do_merge(I2, J2, d2, (cnt - 2) % 3);
    if (warp_m == 1) do_epi(I1, J1, (cnt - 1) % 3);
    __syncthreads();
    do_merge(I1, J1, d1, (cnt - 1) % 3);
}

// ---------------- fused finalize: per-row lse - pos, chip-wide double sum ----------
__global__ __launch_bounds__(256) void finalize_all(float* __restrict__ out) {
    __shared__ double red[256];
    __shared__ int s_last;
    const int tid = threadIdx.x;
    const int row = blockIdx.x * 256 + tid;
    const int R = row >> 7;
    const int rl = row & 127;
    const float* ps = g_ps + (size_t)R * NP * 128 + rl;
    float S = 0.f;
#pragma unroll 8
    for (int c = 0; c < NP; ++c) S += ps[c * 128];
    red[tid] = (double)((__log2f(S) - g_pos[row]) * 0.69314718055994531f);
    __syncthreads();
    for (int s = 128; s > 0; s >>= 1) {
        if (tid < s) red[tid] += red[tid + s];
        __syncthreads();
    }
    if (tid == 0) {
        g_part[blockIdx.x] = red[0];
        __threadfence();
        unsigned int old = atomicAdd(&g_cnt, 1u);
        s_last = (((old + 1) & 31) == 0);
    }
    __syncthreads();
    if (s_last && tid < 32) {
        double v = g_part[tid];
#pragma unroll
        for (int off = 16; off > 0; off >>= 1)
            v += __shfl_down_sync(0xffffffffu, v, off);
        if (tid == 0) out[0] = (float)(v / (double)NN);
    }
}

extern "C" void kernel_launch(void* const* d_in, const int* in_sizes, int n_in,
                              void* d_out, int out_size) {
    const float* h_i = (const float*)d_in[0];
    const float* h_j = (const float*)d_in[1];
    (void)in_sizes; (void)n_in; (void)out_size;

    static bool attr_set = false;
    if (!attr_set) {
        cudaFuncSetAttribute(gemm_lse_sym, cudaFuncAttributeMaxDynamicSharedMemorySize,
                             SMEM_BYTES);
        attr_set = true;
    }

    convert_bf16<<<2048, 256>>>(h_i, h_j);
    gemm_lse_sym<<<NCTA, 256, SMEM_BYTES>>>();
    finalize_all<<<32, 256>>>((float*)d_out);
}

// round 16
// speedup vs baseline: 2.0552x; 1.3433x over previous
#include <cuda_runtime.h>
#include <cuda_bf16.h>
#include <math_constants.h>
#include <cstdint>

// ---------------- problem constants ----------------
#define NN 8192      // 2*B rows
#define BB 4096
#define DD 256
#define NP 64        // 128-row panels
#define NCTA 148     // 148 CTAs; 2080 = 148*14 + 8 upper-tri tiles
#define CREF 192.0f  // fixed log2-domain exp reference

// ---------------- device scratch ----------------
__device__ int8_t g_hq[NN * DD];               // per-row int8 quant of sqrt(2*log2e)*h
__device__ float  g_scale[NN];                 // per-row sigma (log2 units per count)
__device__ float  g_ps[NP * NP * 128];         // per (rowPanel,colPanel) partial sum
__device__ float  g_pos[NN];                   // positive logit minus CREF
__device__ double g_part[32];
__device__ unsigned int g_cnt;

__device__ __forceinline__ uint32_t smem_u32(const void* p) {
    uint32_t a;
    asm("{ .reg .u64 t; cvta.to.shared.u64 t, %1; cvt.u32.u64 %0, t; }" : "=r"(a) : "l"(p));
    return a;
}

__device__ __forceinline__ void ldsm_x4(uint32_t* r, uint32_t addr) {
    asm volatile("ldmatrix.sync.aligned.m8n8.x4.shared.b16 {%0,%1,%2,%3}, [%4];"
        : "=r"(r[0]), "=r"(r[1]), "=r"(r[2]), "=r"(r[3]) : "r"(addr));
}

__device__ __forceinline__ void imma16832(int* c, const uint32_t* a,
                                          uint32_t b0, uint32_t b1) {
    asm volatile(
        "mma.sync.aligned.m16n8k32.row.col.s32.s8.s8.s32 "
        "{%0,%1,%2,%3}, {%4,%5,%6,%7}, {%8,%9}, {%0,%1,%2,%3};"
        : "+r"(c[0]), "+r"(c[1]), "+r"(c[2]), "+r"(c[3])
        : "r"(a[0]), "r"(a[1]), "r"(a[2]), "r"(a[3]), "r"(b0), "r"(b1));
}

__device__ __forceinline__ void imma16832_z(int* d, const uint32_t* a,
                                            uint32_t b0, uint32_t b1) {
    asm volatile(
        "mma.sync.aligned.m16n8k32.row.col.s32.s8.s8.s32 "
        "{%0,%1,%2,%3}, {%4,%5,%6,%7}, {%8,%9}, {%10,%11,%12,%13};"
        : "=r"(d[0]), "=r"(d[1]), "=r"(d[2]), "=r"(d[3])
        : "r"(a[0]), "r"(a[1]), "r"(a[2]), "r"(a[3]), "r"(b0), "r"(b1),
          "r"(0), "r"(0), "r"(0), "r"(0));
}

__device__ __forceinline__ float fex2(float x) {
    float y;
    asm("ex2.approx.f32 %0, %1;" : "=f"(y) : "f"(x));
    return y;
}

// int8 tile: 128 rows x 256 bytes; swizzle XOR bits[6:4] by row&7 (ldsm conflict-free:
// (addr>>4)&7 = (kb>>4 ^ r)&7 distinct over 8 rows)
#define SW256(r, kb) ((r) * 256 + ((kb) ^ (((r) & 7) << 4)))

// 128 rows x 256 bytes = 2048 16B chunks; 256 threads x 8
__device__ __forceinline__ void load_tile_q8(uint32_t sdst, const int8_t* gbase,
                                             int tid) {
#pragma unroll
    for (int i = 0; i < 8; ++i) {
        int c = tid + i * 256;
        int r = c >> 4;
        int kb = (c & 15) << 4;
        uint32_t dst = sdst + SW256(r, kb);
        const char* src = (const char*)gbase + (size_t)r * DD + kb;
        asm volatile("cp.async.cg.shared.global [%0], [%1], 16;" :: "r"(dst), "l"(src));
    }
}

// 128 floats of per-row scale -> smem (threads 0..31, 16B each)
__device__ __forceinline__ void load_scales(uint32_t sdst, const float* gsrc, int tid) {
    if (tid < 32) {
        uint32_t dst = sdst + tid * 16;
        const char* src = (const char*)(gsrc + tid * 4);
        asm volatile("cp.async.ca.shared.global [%0], [%1], 16;" :: "r"(dst), "l"(src));
    }
}

// ---------------- kernel 0: fp32 -> per-row int8 quant (one warp per row) ----------
__global__ __launch_bounds__(256) void convert_q8(const float* __restrict__ h_i,
                                                  const float* __restrict__ h_j) {
    const int lane = threadIdx.x & 31;
    const int row = blockIdx.x * 8 + (threadIdx.x >> 5);   // grid 1024
    const float* src = (row < BB) ? h_i + (size_t)row * DD : h_j + (size_t)(row - BB) * DD;
    const float s = 1.6986436f;               // sqrt(2 * log2(e))
    float4 x0 = *(const float4*)(src + lane * 8);
    float4 x1 = *(const float4*)(src + lane * 8 + 4);
    float v[8] = {x0.x * s, x0.y * s, x0.z * s, x0.w * s,
                  x1.x * s, x1.y * s, x1.z * s, x1.w * s};
    float m = fabsf(v[0]);
#pragma unroll
    for (int k = 1; k < 8; ++k) m = fmaxf(m, fabsf(v[k]));
#pragma unroll
    for (int off = 16; off > 0; off >>= 1)
        m = fmaxf(m, __shfl_xor_sync(0xffffffffu, m, off));
    m = fmaxf(m, 1e-30f);
    const float inv = 127.0f / m;
    uint32_t w0 = 0, w1 = 0;
#pragma unroll
    for (int k = 0; k < 4; ++k) {
        w0 |= ((uint32_t)(__float2int_rn(v[k] * inv)) & 0xffu) << (k * 8);
        w1 |= ((uint32_t)(__float2int_rn(v[k + 4] * inv)) & 0xffu) << (k * 8);
    }
    uint2 w;
    w.x = w0; w.y = w1;
    ((uint2*)(g_hq + (size_t)row * DD))[lane] = w;
    if (lane == 0) g_scale[row] = m * (1.0f / 127.0f);
}

// ---------------- kernel 1: symmetric int8 GEMM, R12 control flow ----------------
// smem: A 32K | B0 32K | B1 32K | sA 512 | sB0 512 | sB1 512 | rowS[2][512] 4K | colS[2][256] 2K
#define OFF_SA   98304
#define OFF_SB0  98816
#define OFF_SB1  99328
#define OFF_ROWS 99840
#define OFF_COLS (OFF_ROWS + 4096)
#define SMEM_BYTES (OFF_COLS + 2048)   // 105984

__global__ __launch_bounds__(256, 1) void gemm_lse_sym() {
    extern __shared__ char smem[];
    const uint32_t sb = smem_u32(smem);
    const uint32_t sbA = sb;
    const uint32_t sbB0 = sb + 32768;
    const uint32_t sbB1 = sb + 65536;
    const float* sAs = (const float*)(smem + OFF_SA);
    const float* sB0s = (const float*)(smem + OFF_SB0);
    const float* sB1s = (const float*)(smem + OFF_SB1);
    float* rowSb = (float*)(smem + OFF_ROWS);   // [2 parity][4 slabs][128]
    float* colSb = (float*)(smem + OFF_COLS);   // [2 parity][2 slabs][128]

    const int tid = threadIdx.x;
    const int lane = tid & 31;
    const int wid = tid >> 5;
    const int warp_m = wid >> 2;
    const int warp_n = wid & 3;

    // per-CTA contiguous range of upper-tri tiles (2080 = 148*14 + 8)
    const int cta = blockIdx.x;
    const int cnt = 14 + (cta < 8 ? 1 : 0);
    int rem = cta * 14 + (cta < 8 ? cta : 8);
    int I = 0, L = NP;
    while (rem >= L) { rem -= L; ++I; --L; }
    int J = I + rem;

    load_tile_q8(sbA, g_hq + (size_t)I * 128 * DD, tid);
    load_scales(sb + OFF_SA, g_scale + I * 128, tid);
    load_tile_q8(sbB0, g_hq + (size_t)J * 128 * DD, tid);
    load_scales(sb + OFF_SB0, g_scale + J * 128, tid);
    asm volatile("cp.async.commit_group;");

    const int lrA = (lane & 7) + ((lane >> 3) & 1) * 8;
    const int kA  = (lane >> 4) * 16;
    const int lnB = (lane & 7) + ((lane >> 4) << 3);
    const int kB  = ((lane >> 3) & 1) * 16;
    const int rquad = lane >> 2;
    const int cquad = (lane & 3) * 2;

    int Ip = 0, Jp = 0;
    bool diagPrev = true;

    for (int t = 0; t < cnt; ++t) {
        const bool last = (t == cnt - 1);
        int In = I, Jn = J + 1;
        if (Jn == NP) { In = I + 1; Jn = In; }

        const uint32_t sbB = (t & 1) ? sbB1 : sbB0;
        const float* sBs = (t & 1) ? sB1s : sB0s;
        if (!last) {
            load_tile_q8((t & 1) ? sbB0 : sbB1, g_hq + (size_t)Jn * 128 * DD, tid);
            load_scales(sb + ((t & 1) ? OFF_SB0 : OFF_SB1), g_scale + Jn * 128, tid);
            asm volatile("cp.async.commit_group;");
            asm volatile("cp.async.wait_group 1;");
        } else {
            asm volatile("cp.async.wait_group 0;");
        }
        __syncthreads();   // single per-tile barrier

        // deferred merge of tile t-1
        if (t > 0) {
            const float* rS = rowSb + ((t - 1) & 1) * 512;
            const float* cS = colSb + ((t - 1) & 1) * 256;
            if (tid < 128) {
                g_ps[((size_t)Ip * NP + Jp) * 128 + tid] =
                    rS[tid] + rS[128 + tid] + rS[256 + tid] + rS[384 + tid];
            } else if (!diagPrev) {
                const int cl = tid - 128;
                g_ps[((size_t)Jp * NP + Ip) * 128 + cl] = cS[cl] + cS[128 + cl];
            }
        }

        int c[4][4][4];
#pragma unroll
        for (int ks = 0; ks < 8; ++ks) {
            uint32_t a[4][4], b[2][4];
#pragma unroll
            for (int mt = 0; mt < 4; ++mt)
                ldsm_x4(a[mt], sbA + SW256(warp_m * 64 + mt * 16 + lrA, ks * 32 + kA));
#pragma unroll
            for (int p = 0; p < 2; ++p)
                ldsm_x4(b[p], sbB + SW256(warp_n * 32 + p * 16 + lnB, ks * 32 + kB));
#pragma unroll
            for (int mt = 0; mt < 4; ++mt)
#pragma unroll
                for (int nt = 0; nt < 4; ++nt) {
                    if (ks == 0)
                        imma16832_z(c[mt][nt], a[mt],
                                    b[nt >> 1][(nt & 1) * 2], b[nt >> 1][(nt & 1) * 2 + 1]);
                    else
                        imma16832(c[mt][nt], a[mt],
                                  b[nt >> 1][(nt & 1) * 2], b[nt >> 1][(nt & 1) * 2 + 1]);
                }
        }

        const bool diagT = (J == I);
        const bool posT  = (J == I + NP / 2);
        const bool special = diagT | posT;

        // per-thread row/col scales
        float si[8], sj[8];
#pragma unroll
        for (int g = 0; g < 8; ++g)
            si[g] = sAs[warp_m * 64 + (g >> 1) * 16 + rquad + (g & 1) * 8];
#pragma unroll
        for (int i = 0; i < 8; ++i)
            sj[i] = sBs[warp_n * 32 + (i >> 1) * 8 + cquad + (i & 1)];

        // scale + mask + exp, in place (store float bits into the int accumulators)
#pragma unroll
        for (int mt = 0; mt < 4; ++mt)
#pragma unroll
            for (int jj = 0; jj < 2; ++jj) {
                const float svi = si[mt * 2 + jj];
                const int rloc = warp_m * 64 + mt * 16 + rquad + jj * 8;
#pragma unroll
                for (int nt = 0; nt < 4; ++nt)
#pragma unroll
                    for (int jc = 0; jc < 2; ++jc) {
                        float f = (float)c[mt][nt][jj * 2 + jc];
                        float v = fmaf(f * svi, sj[nt * 2 + jc], -CREF);
                        if (special) {
                            const int cloc = warp_n * 32 + nt * 8 + cquad + jc;
                            if (cloc == rloc) {
                                if (posT) {
                                    g_pos[I * 128 + rloc] = v;   // pos - CREF
                                    g_pos[J * 128 + rloc] = v;
                                } else {
                                    v = -CUDART_INF_F;
                                }
                            }
                        }
                        c[mt][nt][jj * 2 + jc] = __float_as_int(fex2(v));
                    }
            }

        float* rS = rowSb + (t & 1) * 512;
        float* cS = colSb + (t & 1) * 256;

#pragma unroll
        for (int mt = 0; mt < 4; ++mt)
#pragma unroll
            for (int jj = 0; jj < 2; ++jj) {
                float s = 0.f;
#pragma unroll
                for (int nt = 0; nt < 4; ++nt)
#pragma unroll
                    for (int jc = 0; jc < 2; ++jc)
                        s += __int_as_float(c[mt][nt][jj * 2 + jc]);
                s += __shfl_xor_sync(0xffffffffu, s, 1);
                s += __shfl_xor_sync(0xffffffffu, s, 2);
                if ((lane & 3) == 0) {
                    const int rloc = warp_m * 64 + mt * 16 + rquad + jj * 8;
                    rS[warp_n * 128 + rloc] = s;
                }
            }

        if (!diagT) {
#pragma unroll
            for (int nt = 0; nt < 4; ++nt)
#pragma unroll
                for (int jc = 0; jc < 2; ++jc) {
                    float cs = 0.f;
#pragma unroll
                    for (int mt = 0; mt < 4; ++mt)
#pragma unroll
                        for (int jj = 0; jj < 2; ++jj)
                            cs += __int_as_float(c[mt][nt][jj * 2 + jc]);
                    cs += __shfl_xor_sync(0xffffffffu, cs, 4);
                    cs += __shfl_xor_sync(0xffffffffu, cs, 8);
                    cs += __shfl_xor_sync(0xffffffffu, cs, 16);
                    if (lane < 4) {
                        const int cloc = warp_n * 32 + nt * 8 + (lane & 3) * 2 + jc;
                        cS[warp_m * 128 + cloc] = cs;
                    }
                }
        }

        if (!last && In != I) {   // A-panel advance: all warps past this tile's ldsm
            __syncthreads();
            load_tile_q8(sbA, g_hq + (size_t)In * 128 * DD, tid);
            load_scales(sb + OFF_SA, g_scale + In * 128, tid);
            asm volatile("cp.async.commit_group;");
        }
        Ip = I; Jp = J; diagPrev = diagT;
        I = In; J = Jn;
    }

    // final tile's merge
    __syncthreads();
    {
        const float* rS = rowSb + ((cnt - 1) & 1) * 512;
        const float* cS = colSb + ((cnt - 1) & 1) * 256;
        if (tid < 128) {
            g_ps[((size_t)Ip * NP + Jp) * 128 + tid] =
                rS[tid] + rS[128 + tid] + rS[256 + tid] + rS[384 + tid];
        } else if (!diagPrev) {
            const int cl = tid - 128;
            g_ps[((size_t)Jp * NP + Ip) * 128 + cl] = cS[cl] + cS[128 + cl];
        }
    }
}

// ---------------- fused finalize: per-row lse - pos, chip-wide double sum ----------
__global__ __launch_bounds__(256) void finalize_all(float* __restrict__ out) {
    __shared__ double red[256];
    __shared__ int s_last;
    const int tid = threadIdx.x;
    const int row = blockIdx.x * 256 + tid;
    const int R = row >> 7;
    const int rl = row & 127;
    const float* ps = g_ps + (size_t)R * NP * 128 + rl;
    float S = 0.f;
#pragma unroll 8
    for (int c = 0; c < NP; ++c) S += ps[c * 128];
    // g_pos holds (pos - CREF); S sums 2^(v - CREF): CREF cancels.
    red[tid] = (double)((__log2f(S) - g_pos[row]) * 0.69314718055994531f);
    __syncthreads();
    for (int s = 128; s > 0; s >>= 1) {
        if (tid < s) red[tid] += red[tid + s];
        __syncthreads();
    }
    if (tid == 0) {
        g_part[blockIdx.x] = red[0];
        __threadfence();
        unsigned int old = atomicAdd(&g_cnt, 1u);
        s_last = (((old + 1) & 31) == 0);
    }
    __syncthreads();
    if (s_last && tid < 32) {
        double v = g_part[tid];
#pragma unroll
        for (int off = 16; off > 0; off >>= 1)
            v += __shfl_down_sync(0xffffffffu, v, off);
        if (tid == 0) out[0] = (float)(v / (double)NN);
    }
}

extern "C" void kernel_launch(void* const* d_in, const int* in_sizes, int n_in,
                              void* d_out, int out_size) {
    const float* h_i = (const float*)d_in[0];
    const float* h_j = (const float*)d_in[1];
    (void)in_sizes; (void)n_in; (void)out_size;

    static bool attr_set = false;
    if (!attr_set) {
        cudaFuncSetAttribute(gemm_lse_sym, cudaFuncAttributeMaxDynamicSharedMemorySize,
                             SMEM_BYTES);
        attr_set = true;
    }

    convert_q8<<<1024, 256>>>(h_i, h_j);
    gemm_lse_sym<<<NCTA, 256, SMEM_BYTES>>>();
    finalize_all<<<32, 256>>>((float*)d_out);
}